// round 8
// baseline (speedup 1.0000x reference)
#include <cuda_runtime.h>
#include <math.h>

#define NC 16
#define MARGIN_F 0.3f
#define EPS_F 1e-8f
#define NBLK 256
#define NTHR 256

// ---------------- device-global scratch (no allocations allowed) -----------
// Counters/flags are reset by the LAST block each run -> clean per graph replay.
__device__ float        g_D16[NC * NC];
__device__ float        g_pr[NBLK];          // per-block rank partial
__device__ float        g_pp[NBLK];          // per-block perplexity partial
__device__ unsigned int g_pc[NBLK];          // per-block valid count
__device__ int          g_dist_cnt = 0;
__device__ int          g_ready    = 0;
__device__ int          g_done     = 0;

__device__ __forceinline__ float ldcg_f(const float* p) {
    float v; asm volatile("ld.global.cg.f32 %0, [%1];" : "=f"(v) : "l"(p)); return v;
}
__device__ __forceinline__ int ldcg_i(const int* p) {
    int v; asm volatile("ld.global.cg.s32 %0, [%1];" : "=r"(v) : "l"(p)); return v;
}
__device__ __forceinline__ unsigned ldcg_u(const unsigned* p) {
    unsigned v; asm volatile("ld.global.cg.u32 %0, [%1];" : "=r"(v) : "l"(p)); return v;
}

__global__ void __launch_bounds__(NTHR) k_fused(
    const float* __restrict__ x,        // inputs [B, D]
    const int*   __restrict__ targets,  // targets_mat [B] (int32: JAX downcast)
    const int*   __restrict__ ua,       // user_answers [T,3] (int32)
    float*       __restrict__ out,
    int B, int D, int T, int out_n)
{
    __shared__ int    s_first[NC];
    __shared__ float  sD[NC * NC];
    __shared__ float  sr0[NTHR / 32], sr1[NTHR / 32], sr2[NTHR / 32];
    __shared__ double dr[NTHR / 32], dp[NTHR / 32];
    __shared__ unsigned long long dc[NTHR / 32];
    __shared__ int    s_last;

    const int tid = threadIdx.x;
    const int bid = blockIdx.x;
    const int STRIDE = NBLK * NTHR;

    // ---- Phase 0: prefetch this thread's triplets (independent of everything;
    //      DRAM latency hides under the scan + dot below) ---------------------
    int t0 = bid * NTHR + tid;
    int3 tr[2]; bool hv[2];
#pragma unroll
    for (int u = 0; u < 2; u++) {
        int t = t0 + u * STRIDE;
        hv[u] = (t < T);
        if (hv[u]) {
            tr[u].x = ua[3 * t + 0];
            tr[u].y = ua[3 * t + 1];
            tr[u].z = ua[3 * t + 2];
        } else {
            tr[u].x = tr[u].y = tr[u].z = -1;
        }
    }

    // ---- Phase 1: first-occurrence scan (guarded atomics: ~94% skipped) ----
    if (tid < NC) s_first[tid] = B;
    __syncthreads();
    for (int i = tid; i < B; i += NTHR) {
        unsigned int c = (unsigned int)targets[i];
        if (c < NC && i < s_first[c])        // racy read is safe: monotone min
            atomicMin(&s_first[c], i);
    }
    __syncthreads();

    // ---- Phase 2: this block computes dist for pair (bid>>4, bid&15) ------
    {
        int i = bid >> 4, j = bid & 15;
        int fi = s_first[i]; if (fi >= B) fi = 0;   // argmax-over-all-false == 0
        int fj = s_first[j]; if (fj >= B) fj = 0;
        const float4* xi4 = (const float4*)(x + (size_t)fi * (size_t)D);
        const float4* xj4 = (const float4*)(x + (size_t)fj * (size_t)D);

        float sii = 0.f, sjj = 0.f, sij = 0.f;
        int nv4 = D >> 2;
        for (int k = tid; k < nv4; k += NTHR) {
            float4 a = xi4[k];
            float4 b = xj4[k];
            sii += a.x * a.x + a.y * a.y + a.z * a.z + a.w * a.w;
            sjj += b.x * b.x + b.y * b.y + b.z * b.z + b.w * b.w;
            sij += a.x * b.x + a.y * b.y + a.z * b.z + a.w * b.w;
        }
        for (int off = 16; off > 0; off >>= 1) {
            sii += __shfl_down_sync(0xFFFFFFFFu, sii, off);
            sjj += __shfl_down_sync(0xFFFFFFFFu, sjj, off);
            sij += __shfl_down_sync(0xFFFFFFFFu, sij, off);
        }
        int w = tid >> 5, l = tid & 31;
        if (l == 0) { sr0[w] = sii; sr1[w] = sjj; sr2[w] = sij; }
        __syncthreads();
        if (tid == 0) {
            float a = 0.f, b = 0.f, c = 0.f;
            for (int w2 = 0; w2 < NTHR / 32; w2++) { a += sr0[w2]; b += sr1[w2]; c += sr2[w2]; }
            float d2 = fmaxf(a + b - 2.0f * c, 1e-12f);
            g_D16[bid] = sqrtf(d2);
            __threadfence();                       // publish before counting
            int old = atomicAdd(&g_dist_cnt, 1);
            if (old == NBLK - 1) atomicExch(&g_ready, 1);   // single flag set
        }
    }

    // ---- Phase 3: barrier — PLAIN-LOAD spin on flag (no RMW storm) --------
    if (tid == 0) {
        volatile int* vr = &g_ready;
        while (*vr == 0) { __nanosleep(64); }
    }
    __syncthreads();
    __threadfence();
    if (tid < NC * NC) sD[tid] = ldcg_f(&g_D16[tid]);   // bypass L1 (not coherent)
    __syncthreads();

    // ---- Phase 4: evaluate triplets (float partials; <=3 per thread) ------
    float rsum = 0.f, psum = 0.f;
    unsigned int cnt = 0;
#pragma unroll
    for (int u = 0; u < 2; u++) {
        if (!hv[u]) continue;
        unsigned int ca = (unsigned int)tr[u].x;
        unsigned int cp = (unsigned int)tr[u].y;
        unsigned int cn = (unsigned int)tr[u].z;
        bool ok = (ca < NC) && (cp < NC) && (cn < NC) &&
                  (s_first[ca] < B) && (s_first[cp] < B) && (s_first[cn] < B);
        if (ok) {
            float dap = sD[ca * NC + cp];
            float dan = sD[ca * NC + cn];
            rsum += fmaxf(dap - dan + MARGIN_F, 0.0f);
            float sap = 1.0f / (dap + 1.0f);
            float san = 1.0f / (dan + 1.0f);
            psum += -logf(sap / (sap + san) + EPS_F);
            cnt++;
        }
    }
    for (int t = t0 + 2 * STRIDE; t < T; t += STRIDE) {   // safety for other shapes
        unsigned int ca = (unsigned int)ua[3 * t + 0];
        unsigned int cp = (unsigned int)ua[3 * t + 1];
        unsigned int cn = (unsigned int)ua[3 * t + 2];
        bool ok = (ca < NC) && (cp < NC) && (cn < NC) &&
                  (s_first[ca] < B) && (s_first[cp] < B) && (s_first[cn] < B);
        if (ok) {
            float dap = sD[ca * NC + cp];
            float dan = sD[ca * NC + cn];
            rsum += fmaxf(dap - dan + MARGIN_F, 0.0f);
            float sap = 1.0f / (dap + 1.0f);
            float san = 1.0f / (dan + 1.0f);
            psum += -logf(sap / (sap + san) + EPS_F);
            cnt++;
        }
    }
    for (int off = 16; off > 0; off >>= 1) {
        rsum += __shfl_down_sync(0xFFFFFFFFu, rsum, off);
        psum += __shfl_down_sync(0xFFFFFFFFu, psum, off);
        cnt  += __shfl_down_sync(0xFFFFFFFFu, cnt,  off);
    }
    {
        int w = tid >> 5, l = tid & 31;
        if (l == 0) { sr0[w] = rsum; sr1[w] = psum; dc[w] = cnt; }
    }
    __syncthreads();

    // ---- Phase 5: plain-store partials + ONE RMW per block ----------------
    if (tid == 0) {
        float R = 0.f, P = 0.f;
        unsigned int C = 0;
        for (int w = 0; w < NTHR / 32; w++) { R += sr0[w]; P += sr1[w]; C += (unsigned)dc[w]; }
        g_pr[bid] = R;
        g_pp[bid] = P;
        g_pc[bid] = C;
        __threadfence();
        int done = atomicAdd(&g_done, 1);
        s_last = (done == NBLK - 1) ? 1 : 0;
    }
    __syncthreads();

    // ---- Phase 6: last block sums 256 partials in parallel & finalizes ----
    if (s_last) {
        __threadfence();
        double r = 0.0, p = 0.0;
        unsigned long long c = 0;
        if (tid < NBLK) {
            r = (double)ldcg_f(&g_pr[tid]);
            p = (double)ldcg_f(&g_pp[tid]);
            c = (unsigned long long)ldcg_u(&g_pc[tid]);
        }
        for (int off = 16; off > 0; off >>= 1) {
            r += __shfl_down_sync(0xFFFFFFFFu, r, off);
            p += __shfl_down_sync(0xFFFFFFFFu, p, off);
            c += __shfl_down_sync(0xFFFFFFFFu, c, off);
        }
        int w = tid >> 5, l = tid & 31;
        if (l == 0) { dr[w] = r; dp[w] = p; dc[w] = c; }
        __syncthreads();
        if (tid == 0) {
            double R = 0.0, P = 0.0;
            unsigned long long C = 0;
            for (int w2 = 0; w2 < NTHR / 32; w2++) { R += dr[w2]; P += dp[w2]; C += dc[w2]; }
            double nv = (double)C;
            if (nv < 1.0) nv = 1.0;
            float lh = (float)(R / nv);
            float lp = (float)(P / nv);
            if (out_n > 0) out[0] = lh + lp;   // W_HUMAN = W_PER = 1
            if (out_n > 1) out[1] = lh;
            if (out_n > 2) out[2] = lp;
            g_dist_cnt = 0;                    // reset for next graph replay
            g_ready    = 0;
            g_done     = 0;
            __threadfence();
        }
    }
}

// ---------------- launch ----------------------------------------------------
// Inputs identified BY SIZE (robust to metadata ordering):
//   inputs       : largest element count              (4096*1024 = 4194304)
//   user_answers : only remaining size divisible by 3 (100000*3  = 300000)
//   targets_mat  : FIRST entry with the minimum size  (4096; targets_sub is
//                  the second 4096 entry, dict order preserved)
extern "C" void kernel_launch(void* const* d_in, const int* in_sizes, int n_in,
                              void* d_out, int out_size) {
    int idx_inputs = -1, idx_ua = -1, idx_tm = -1;
    int max_sz = -1;
    for (int i = 0; i < n_in; i++)
        if (in_sizes[i] > max_sz) { max_sz = in_sizes[i]; idx_inputs = i; }
    for (int i = 0; i < n_in; i++) {
        if (i == idx_inputs) continue;
        if ((in_sizes[i] % 3) == 0) { idx_ua = i; break; }
    }
    int min_sz = 0x7fffffff;
    for (int i = 0; i < n_in; i++) {
        if (i == idx_inputs || i == idx_ua) continue;
        if (in_sizes[i] < min_sz) min_sz = in_sizes[i];
    }
    for (int i = 0; i < n_in; i++) {
        if (i == idx_inputs || i == idx_ua) continue;
        if (in_sizes[i] == min_sz) { idx_tm = i; break; }   // first occurrence
    }
    if (idx_inputs < 0 || idx_ua < 0 || idx_tm < 0) return;

    const float* inputs   = (const float*)d_in[idx_inputs];
    const int*   targets  = (const int*)d_in[idx_tm];
    const int*   user_ans = (const int*)d_in[idx_ua];
    float* out = (float*)d_out;

    int B = in_sizes[idx_tm];
    int D = in_sizes[idx_inputs] / B;
    int T = in_sizes[idx_ua] / 3;

    k_fused<<<NBLK, NTHR>>>(inputs, targets, user_ans, out, B, D, T, out_size);
}